// round 2
// baseline (speedup 1.0000x reference)
#include <cuda_runtime.h>
#include <cuda_bf16.h>
#include <math.h>

#define TT 2048
#define DM 2048
#define NH 16
#define DH 128

// ---------------- scratch (static device globals; no allocation) -------------
__device__ float g_h[(size_t)TT * DM];    // RMSNorm output
__device__ float g_q[(size_t)TT * DM];
__device__ float g_k[(size_t)TT * DM];
__device__ float g_v[(size_t)TT * DM];
__device__ float g_att[(size_t)TT * DM];  // attention output (pre O-proj)

// ---------------- RMSNorm ----------------------------------------------------
__global__ __launch_bounds__(256) void rmsnorm_kernel(const float* __restrict__ x,
                                                      const float* __restrict__ w) {
    __shared__ float red[256];
    const int row = blockIdx.x;
    const int tid = threadIdx.x;
    const float* xr = x + (size_t)row * DM;
    float s = 0.f;
    for (int i = tid; i < DM; i += 256) { float v = xr[i]; s += v * v; }
    red[tid] = s;
    __syncthreads();
    for (int o = 128; o > 0; o >>= 1) {
        if (tid < o) red[tid] += red[tid + o];
        __syncthreads();
    }
    const float inv = rsqrtf(red[0] / (float)DM + 1e-5f);
    float* hr = g_h + (size_t)row * DM;
    for (int i = tid; i < DM; i += 256) hr[i] = w[i] * xr[i] * inv;
}

// ---------------- NT SGEMM: C[M,N] = A[M,K] * B[N,K]^T (+ optional residual) -
// M = N = K = 2048 fixed. 128x128 tile, BK=8, 256 threads, 8x8 per thread.
__global__ __launch_bounds__(256) void gemm_nt_kernel(const float* __restrict__ A,
                                                      const float* __restrict__ B,
                                                      float* __restrict__ C,
                                                      const float* __restrict__ R) {
    __shared__ float As[8][128];
    __shared__ float Bs[8][128];
    const int tid = threadIdx.x;
    const int tx = tid & 15, ty = tid >> 4;
    const int m0 = blockIdx.y * 128, n0 = blockIdx.x * 128;
    const int lr = tid >> 1;          // 0..127
    const int lc = (tid & 1) * 4;     // 0 or 4

    const float* Ap = A + (size_t)(m0 + lr) * DM + lc;
    const float* Bp = B + (size_t)(n0 + lr) * DM + lc;

    float acc[8][8];
#pragma unroll
    for (int i = 0; i < 8; i++)
#pragma unroll
        for (int j = 0; j < 8; j++) acc[i][j] = 0.f;

    for (int k0 = 0; k0 < DM; k0 += 8) {
        float4 a4 = *(const float4*)(Ap + k0);
        float4 b4 = *(const float4*)(Bp + k0);
        As[lc + 0][lr] = a4.x; As[lc + 1][lr] = a4.y;
        As[lc + 2][lr] = a4.z; As[lc + 3][lr] = a4.w;
        Bs[lc + 0][lr] = b4.x; Bs[lc + 1][lr] = b4.y;
        Bs[lc + 2][lr] = b4.z; Bs[lc + 3][lr] = b4.w;
        __syncthreads();
#pragma unroll
        for (int kk = 0; kk < 8; kk++) {
            float a[8], b[8];
            *(float4*)(a)     = *(const float4*)&As[kk][ty * 8];
            *(float4*)(a + 4) = *(const float4*)&As[kk][ty * 8 + 4];
            *(float4*)(b)     = *(const float4*)&Bs[kk][tx * 8];
            *(float4*)(b + 4) = *(const float4*)&Bs[kk][tx * 8 + 4];
#pragma unroll
            for (int i = 0; i < 8; i++)
#pragma unroll
                for (int j = 0; j < 8; j++) acc[i][j] += a[i] * b[j];
        }
        __syncthreads();
    }

#pragma unroll
    for (int i = 0; i < 8; i++) {
        const int m = m0 + ty * 8 + i;
        float* Cp = C + (size_t)m * DM + n0 + tx * 8;
        if (R) {
            const float* Rp = R + (size_t)m * DM + n0 + tx * 8;
            float4 r0 = *(const float4*)(Rp);
            float4 r1 = *(const float4*)(Rp + 4);
            float4 o0 = make_float4(acc[i][0] + r0.x, acc[i][1] + r0.y,
                                    acc[i][2] + r0.z, acc[i][3] + r0.w);
            float4 o1 = make_float4(acc[i][4] + r1.x, acc[i][5] + r1.y,
                                    acc[i][6] + r1.z, acc[i][7] + r1.w);
            *(float4*)(Cp) = o0; *(float4*)(Cp + 4) = o1;
        } else {
            *(float4*)(Cp)     = make_float4(acc[i][0], acc[i][1], acc[i][2], acc[i][3]);
            *(float4*)(Cp + 4) = make_float4(acc[i][4], acc[i][5], acc[i][6], acc[i][7]);
        }
    }
}

// ---------------- RoPE on g_q and g_k (in place) ------------------------------
__global__ __launch_bounds__(256) void rope_kernel(const float* __restrict__ cosb,
                                                   const float* __restrict__ sinb) {
    const int idx = blockIdx.x * 256 + threadIdx.x;  // T * NH * 64 = 2,097,152
    const int t = idx >> 10;
    const int rem = idx & 1023;
    const int h = rem >> 6;
    const int j = rem & 63;
    const size_t base = (size_t)t * DM + h * DH;
    const float c0 = cosb[t * DH + j],      s0 = sinb[t * DH + j];
    const float c1 = cosb[t * DH + 64 + j], s1 = sinb[t * DH + 64 + j];

    float q0 = g_q[base + j], q1 = g_q[base + 64 + j];
    g_q[base + j]      = q0 * c0 - q1 * s0;
    g_q[base + 64 + j] = q1 * c1 + q0 * s1;

    float k0 = g_k[base + j], k1 = g_k[base + 64 + j];
    g_k[base + j]      = k0 * c0 - k1 * s0;
    g_k[base + 64 + j] = k1 * c1 + k0 * s1;
}

// ---------------- causal flash attention --------------------------------------
// grid (32 qtiles, 16 heads), 256 threads. Tiles: 64 queries x 64 keys.
// Smem: Qt[128][68] (d-major, transposed), Kt[128][68] (K transposed; reused
// as V natural [64][128]), Ps[64][68].
#define ATTN_SMEM ((2 * 128 * 68 + 64 * 68) * sizeof(float))

__global__ __launch_bounds__(256) void attn_kernel() {
    extern __shared__ float sm[];
    float* Qt = sm;                   // [128][68]
    float* Kt = sm + 128 * 68;        // [128][68] / as V: [64][128]
    float* Ps = sm + 2 * 128 * 68;    // [64][68]

    const int qt = blockIdx.x, h = blockIdx.y;
    const int tid = threadIdx.x, tx = tid & 15, ty = tid >> 4;
    const int q0 = qt * 64;
    const float scale = 0.088388347648318447f;  // 1/sqrt(128)

    // load Q tile transposed: Qt[d][r]
    const float* Qg = g_q + (size_t)q0 * DM + h * DH;
    for (int i = tid; i < 64 * 32; i += 256) {
        const int r = i & 63, c4 = i >> 6;
        float4 v = *(const float4*)(Qg + (size_t)r * DM + c4 * 4);
        const int d = c4 * 4;
        Qt[(d + 0) * 68 + r] = v.x; Qt[(d + 1) * 68 + r] = v.y;
        Qt[(d + 2) * 68 + r] = v.z; Qt[(d + 3) * 68 + r] = v.w;
    }

    float m_i[4], l_i[4], acc[4][8];
#pragma unroll
    for (int r = 0; r < 4; r++) {
        m_i[r] = -1e30f; l_i[r] = 0.f;
#pragma unroll
        for (int j = 0; j < 8; j++) acc[r][j] = 0.f;
    }

    for (int kt = 0; kt <= qt; kt++) {
        const int k0 = kt * 64;
        __syncthreads();  // protect previous-iteration V reads (and Qt stores, iter 0)
        // load K tile transposed: Kt[d][c]
        const float* Kg = g_k + (size_t)k0 * DM + h * DH;
        for (int i = tid; i < 64 * 32; i += 256) {
            const int r = i & 63, c4 = i >> 6;
            float4 v = *(const float4*)(Kg + (size_t)r * DM + c4 * 4);
            const int d = c4 * 4;
            Kt[(d + 0) * 68 + r] = v.x; Kt[(d + 1) * 68 + r] = v.y;
            Kt[(d + 2) * 68 + r] = v.z; Kt[(d + 3) * 68 + r] = v.w;
        }
        __syncthreads();

        // S = Q K^T  (4x4 per thread)
        float s[4][4];
#pragma unroll
        for (int r = 0; r < 4; r++)
#pragma unroll
            for (int c = 0; c < 4; c++) s[r][c] = 0.f;

#pragma unroll 8
        for (int d = 0; d < DH; d++) {
            float qa[4], ka[4];
            *(float4*)qa = *(const float4*)&Qt[d * 68 + ty * 4];
            *(float4*)ka = *(const float4*)&Kt[d * 68 + tx * 4];
#pragma unroll
            for (int r = 0; r < 4; r++)
#pragma unroll
                for (int c = 0; c < 4; c++) s[r][c] += qa[r] * ka[c];
        }

        // scale + causal mask
#pragma unroll
        for (int r = 0; r < 4; r++) {
            const int qi = q0 + ty * 4 + r;
#pragma unroll
            for (int c = 0; c < 4; c++) {
                const int kj = k0 + tx * 4 + c;
                s[r][c] = (kj > qi) ? -1e30f : s[r][c] * scale;
            }
        }

        // online softmax (row groups of 16 threads over tx)
#pragma unroll
        for (int r = 0; r < 4; r++) {
            float mx = fmaxf(fmaxf(s[r][0], s[r][1]), fmaxf(s[r][2], s[r][3]));
#pragma unroll
            for (int o = 8; o > 0; o >>= 1)
                mx = fmaxf(mx, __shfl_xor_sync(0xffffffffu, mx, o));
            const float mn = fmaxf(m_i[r], mx);
            const float alpha = __expf(m_i[r] - mn);
            m_i[r] = mn;
            float rs = 0.f;
#pragma unroll
            for (int c = 0; c < 4; c++) {
                const float p = __expf(s[r][c] - mn);
                Ps[(ty * 4 + r) * 68 + tx * 4 + c] = p;
                rs += p;
            }
#pragma unroll
            for (int o = 8; o > 0; o >>= 1)
                rs += __shfl_xor_sync(0xffffffffu, rs, o);
            l_i[r] = l_i[r] * alpha + rs;
#pragma unroll
            for (int j = 0; j < 8; j++) acc[r][j] *= alpha;
        }
        __syncthreads();  // Ps written, Kt reads done

        // load V tile natural layout into Kt buffer: V[c][d]
        const float* Vg = g_v + (size_t)k0 * DM + h * DH;
        for (int i = tid; i < 64 * 32; i += 256) {
            ((float4*)Kt)[i] = *(const float4*)(Vg + (size_t)(i >> 5) * DM + (i & 31) * 4);
        }
        __syncthreads();

        // O += P V   (4 rows x 8 dims per thread)
#pragma unroll 4
        for (int c = 0; c < 64; c++) {
            float4 v0 = *(const float4*)&Kt[c * DH + tx * 8];
            float4 v1 = *(const float4*)&Kt[c * DH + tx * 8 + 4];
#pragma unroll
            for (int r = 0; r < 4; r++) {
                const float p = Ps[(ty * 4 + r) * 68 + c];
                acc[r][0] += p * v0.x; acc[r][1] += p * v0.y;
                acc[r][2] += p * v0.z; acc[r][3] += p * v0.w;
                acc[r][4] += p * v1.x; acc[r][5] += p * v1.y;
                acc[r][6] += p * v1.z; acc[r][7] += p * v1.w;
            }
        }
    }

    // epilogue
#pragma unroll
    for (int r = 0; r < 4; r++) {
        const float invl = 1.f / l_i[r];
        float* Og = g_att + (size_t)(q0 + ty * 4 + r) * DM + h * DH + tx * 8;
        *(float4*)(Og)     = make_float4(acc[r][0] * invl, acc[r][1] * invl,
                                         acc[r][2] * invl, acc[r][3] * invl);
        *(float4*)(Og + 4) = make_float4(acc[r][4] * invl, acc[r][5] * invl,
                                         acc[r][6] * invl, acc[r][7] * invl);
    }
}

// ---------------- launcher ----------------------------------------------------
extern "C" void kernel_launch(void* const* d_in, const int* in_sizes, int n_in,
                              void* d_out, int out_size) {
    const float* x    = (const float*)d_in[0];
    const float* w_ln = (const float*)d_in[1];
    const float* wq   = (const float*)d_in[2];
    const float* wk   = (const float*)d_in[3];
    const float* wv   = (const float*)d_in[4];
    const float* wo   = (const float*)d_in[5];
    const float* cosb = (const float*)d_in[6];
    const float* sinb = (const float*)d_in[7];
    float* out = (float*)d_out;

    // Host-side setup (non-stream APIs; legal during graph capture).
    (void)cudaFuncSetAttribute(attn_kernel,
                               cudaFuncAttributeMaxDynamicSharedMemorySize,
                               (int)ATTN_SMEM);

    float *p_h, *p_q, *p_k, *p_v, *p_att;
    (void)cudaGetSymbolAddress((void**)&p_h, g_h);
    (void)cudaGetSymbolAddress((void**)&p_q, g_q);
    (void)cudaGetSymbolAddress((void**)&p_k, g_k);
    (void)cudaGetSymbolAddress((void**)&p_v, g_v);
    (void)cudaGetSymbolAddress((void**)&p_att, g_att);

    const dim3 gemm_grid(16, 16);

    rmsnorm_kernel<<<TT, 256>>>(x, w_ln);
    gemm_nt_kernel<<<gemm_grid, 256>>>(p_h, wq, p_q, nullptr);
    gemm_nt_kernel<<<gemm_grid, 256>>>(p_h, wk, p_k, nullptr);
    gemm_nt_kernel<<<gemm_grid, 256>>>(p_h, wv, p_v, nullptr);
    rope_kernel<<<(TT * NH * 64) / 256, 256>>>(cosb, sinb);
    attn_kernel<<<dim3(TT / 64, NH), 256, ATTN_SMEM>>>();
    gemm_nt_kernel<<<gemm_grid, 256>>>(p_att, wo, out, x);
}

// round 4
// speedup vs baseline: 1.5133x; 1.5133x over previous
#include <cuda_runtime.h>
#include <cuda_bf16.h>
#include <cstdint>
#include <math.h>

#define TT 2048
#define DM 2048
#define NH 16
#define DH 128

// ===================== scratch (static device globals) =======================
__device__ float g_q[(size_t)TT * DM];
__device__ float g_k[(size_t)TT * DM];
__device__ float g_v[(size_t)TT * DM];
__device__ __nv_bfloat16 g_hh[(size_t)TT * DM];   // rmsnorm out, hi
__device__ __nv_bfloat16 g_hl[(size_t)TT * DM];   // rmsnorm out, lo
__device__ __nv_bfloat16 g_ath[(size_t)TT * DM];  // attention out, hi
__device__ __nv_bfloat16 g_atl[(size_t)TT * DM];  // attention out, lo
__device__ __nv_bfloat16 g_wqh[(size_t)DM * DM], g_wql[(size_t)DM * DM];
__device__ __nv_bfloat16 g_wkh[(size_t)DM * DM], g_wkl[(size_t)DM * DM];
__device__ __nv_bfloat16 g_wvh[(size_t)DM * DM], g_wvl[(size_t)DM * DM];
__device__ __nv_bfloat16 g_woh[(size_t)DM * DM], g_wol[(size_t)DM * DM];

// ===================== mma.sync bf16 (m16n8k16, fp32 acc) ====================
__device__ __forceinline__ void mma_bf16(float* c, uint32_t a0, uint32_t a1,
                                         uint32_t a2, uint32_t a3,
                                         uint32_t b0, uint32_t b1) {
    asm volatile(
        "mma.sync.aligned.m16n8k16.row.col.f32.bf16.bf16.f32 "
        "{%0,%1,%2,%3}, {%4,%5,%6,%7}, {%8,%9}, {%0,%1,%2,%3};"
        : "+f"(c[0]), "+f"(c[1]), "+f"(c[2]), "+f"(c[3])
        : "r"(a0), "r"(a1), "r"(a2), "r"(a3), "r"(b0), "r"(b1));
}

// ===================== split fp32 -> bf16 hi/lo ==============================
__global__ __launch_bounds__(256) void split_kernel(const float* __restrict__ X,
                                                    __nv_bfloat16* __restrict__ Hi,
                                                    __nv_bfloat16* __restrict__ Lo) {
    const int i = (blockIdx.x * 256 + threadIdx.x) * 4;
    float4 v = *(const float4*)(X + i);
    float f[4] = {v.x, v.y, v.z, v.w};
    unsigned short hb[4], lb[4];
#pragma unroll
    for (int j = 0; j < 4; j++) {
        __nv_bfloat16 h = __float2bfloat16(f[j]);
        __nv_bfloat16 l = __float2bfloat16(f[j] - __bfloat162float(h));
        hb[j] = __bfloat16_as_ushort(h);
        lb[j] = __bfloat16_as_ushort(l);
    }
    uint2 hv, lv;
    hv.x = (uint32_t)hb[0] | ((uint32_t)hb[1] << 16);
    hv.y = (uint32_t)hb[2] | ((uint32_t)hb[3] << 16);
    lv.x = (uint32_t)lb[0] | ((uint32_t)lb[1] << 16);
    lv.y = (uint32_t)lb[2] | ((uint32_t)lb[3] << 16);
    *(uint2*)(Hi + i) = hv;
    *(uint2*)(Lo + i) = lv;
}

// ===================== RMSNorm (emits bf16 hi/lo) ============================
__global__ __launch_bounds__(256) void rmsnorm_kernel(const float* __restrict__ x,
                                                      const float* __restrict__ w) {
    __shared__ float red[256];
    const int row = blockIdx.x;
    const int tid = threadIdx.x;
    const float* xr = x + (size_t)row * DM;
    float s = 0.f;
    for (int i = tid; i < DM; i += 256) { float v = xr[i]; s += v * v; }
    red[tid] = s;
    __syncthreads();
    for (int o = 128; o > 0; o >>= 1) {
        if (tid < o) red[tid] += red[tid + o];
        __syncthreads();
    }
    const float inv = rsqrtf(red[0] / (float)DM + 1e-5f);
    __nv_bfloat16* hh = g_hh + (size_t)row * DM;
    __nv_bfloat16* hl = g_hl + (size_t)row * DM;
    for (int i = tid; i < DM; i += 256) {
        float y = w[i] * xr[i] * inv;
        __nv_bfloat16 h = __float2bfloat16(y);
        hh[i] = h;
        hl[i] = __float2bfloat16(y - __bfloat162float(h));
    }
}

// ===================== split-bf16 tensor GEMM (mma.sync) =====================
// C[M,N] = (Ah+Al)[M,K] * (Bh+Bl)[N,K]^T  (dropping Al*Bl), optional residual.
// CTA 128x128, BK=32, 8 warps in 2(M)x4(N), warp tile 64x32.
#define SPAD 40  // row stride in bf16 (80 bytes = 20 banks, conflict-free)

__device__ __forceinline__ void load_tile(__nv_bfloat16 (*S)[SPAD],
                                          const __nv_bfloat16* g,
                                          int row0, int k0, int tid) {
#pragma unroll
    for (int t = 0; t < 2; t++) {
        const int idx = t * 256 + tid;     // 0..511
        const int r = idx >> 2, c = idx & 3;
        uint4 v = *(const uint4*)(g + (size_t)(row0 + r) * DM + k0 + c * 8);
        *(uint4*)&S[r][c * 8] = v;
    }
}

__global__ __launch_bounds__(256) void gemm_mma_kernel(
    const __nv_bfloat16* __restrict__ Ah, const __nv_bfloat16* __restrict__ Al,
    const __nv_bfloat16* __restrict__ Bh, const __nv_bfloat16* __restrict__ Bl,
    float* __restrict__ C, const float* __restrict__ R) {
    __shared__ __nv_bfloat16 As_h[128][SPAD], As_l[128][SPAD];
    __shared__ __nv_bfloat16 Bs_h[128][SPAD], Bs_l[128][SPAD];

    const int tid = threadIdx.x;
    const int wid = tid >> 5, lane = tid & 31;
    const int gg = lane >> 2, tg = lane & 3;
    const int wm = (wid >> 2) * 64, wn = (wid & 3) * 32;
    const int m0 = blockIdx.y * 128, n0 = blockIdx.x * 128;

    float acc[4][4][4];
#pragma unroll
    for (int mt = 0; mt < 4; mt++)
#pragma unroll
        for (int nt = 0; nt < 4; nt++)
#pragma unroll
            for (int j = 0; j < 4; j++) acc[mt][nt][j] = 0.f;

    for (int k0 = 0; k0 < DM; k0 += 32) {
        __syncthreads();
        load_tile(As_h, Ah, m0, k0, tid);
        load_tile(As_l, Al, m0, k0, tid);
        load_tile(Bs_h, Bh, n0, k0, tid);
        load_tile(Bs_l, Bl, n0, k0, tid);
        __syncthreads();

#pragma unroll
        for (int ks = 0; ks < 32; ks += 16) {
            uint32_t ah[4][4], al[4][4], bh[4][2], bl[4][2];
#pragma unroll
            for (int mt = 0; mt < 4; mt++) {
                const int row = wm + mt * 16;
                ah[mt][0] = *(const uint32_t*)&As_h[row + gg][ks + tg * 2];
                ah[mt][1] = *(const uint32_t*)&As_h[row + gg + 8][ks + tg * 2];
                ah[mt][2] = *(const uint32_t*)&As_h[row + gg][ks + tg * 2 + 8];
                ah[mt][3] = *(const uint32_t*)&As_h[row + gg + 8][ks + tg * 2 + 8];
                al[mt][0] = *(const uint32_t*)&As_l[row + gg][ks + tg * 2];
                al[mt][1] = *(const uint32_t*)&As_l[row + gg + 8][ks + tg * 2];
                al[mt][2] = *(const uint32_t*)&As_l[row + gg][ks + tg * 2 + 8];
                al[mt][3] = *(const uint32_t*)&As_l[row + gg + 8][ks + tg * 2 + 8];
            }
#pragma unroll
            for (int nt = 0; nt < 4; nt++) {
                const int col = wn + nt * 8;
                bh[nt][0] = *(const uint32_t*)&Bs_h[col + gg][ks + tg * 2];
                bh[nt][1] = *(const uint32_t*)&Bs_h[col + gg][ks + tg * 2 + 8];
                bl[nt][0] = *(const uint32_t*)&Bs_l[col + gg][ks + tg * 2];
                bl[nt][1] = *(const uint32_t*)&Bs_l[col + gg][ks + tg * 2 + 8];
            }
#pragma unroll
            for (int mt = 0; mt < 4; mt++)
#pragma unroll
                for (int nt = 0; nt < 4; nt++) {
                    mma_bf16(acc[mt][nt], ah[mt][0], ah[mt][1], ah[mt][2], ah[mt][3],
                             bh[nt][0], bh[nt][1]);
                    mma_bf16(acc[mt][nt], ah[mt][0], ah[mt][1], ah[mt][2], ah[mt][3],
                             bl[nt][0], bl[nt][1]);
                    mma_bf16(acc[mt][nt], al[mt][0], al[mt][1], al[mt][2], al[mt][3],
                             bh[nt][0], bh[nt][1]);
                }
        }
    }

    // epilogue: c0,c1 -> row m+gg, cols n+tg*2,+1 ; c2,c3 -> row m+gg+8
#pragma unroll
    for (int mt = 0; mt < 4; mt++) {
        const int mA = m0 + wm + mt * 16 + gg;
        const int mB = mA + 8;
#pragma unroll
        for (int nt = 0; nt < 4; nt++) {
            const int n = n0 + wn + nt * 8 + tg * 2;
            float2 v0 = make_float2(acc[mt][nt][0], acc[mt][nt][1]);
            float2 v1 = make_float2(acc[mt][nt][2], acc[mt][nt][3]);
            if (R) {
                float2 r0 = *(const float2*)(R + (size_t)mA * DM + n);
                float2 r1 = *(const float2*)(R + (size_t)mB * DM + n);
                v0.x += r0.x; v0.y += r0.y;
                v1.x += r1.x; v1.y += r1.y;
            }
            *(float2*)(C + (size_t)mA * DM + n) = v0;
            *(float2*)(C + (size_t)mB * DM + n) = v1;
        }
    }
}

// ===================== RoPE on g_q and g_k (in place) ========================
__global__ __launch_bounds__(256) void rope_kernel(const float* __restrict__ cosb,
                                                   const float* __restrict__ sinb) {
    const int idx = blockIdx.x * 256 + threadIdx.x;
    const int t = idx >> 10;
    const int rem = idx & 1023;
    const int h = rem >> 6;
    const int j = rem & 63;
    const size_t base = (size_t)t * DM + h * DH;
    const float c0 = cosb[t * DH + j],      s0 = sinb[t * DH + j];
    const float c1 = cosb[t * DH + 64 + j], s1 = sinb[t * DH + 64 + j];

    float q0 = g_q[base + j], q1 = g_q[base + 64 + j];
    g_q[base + j]      = q0 * c0 - q1 * s0;
    g_q[base + 64 + j] = q1 * c1 + q0 * s1;

    float k0 = g_k[base + j], k1 = g_k[base + 64 + j];
    g_k[base + j]      = k0 * c0 - k1 * s0;
    g_k[base + 64 + j] = k1 * c1 + k0 * s1;
}

// ===================== causal flash attention (fp32 SIMT) ====================
#define ATTN_SMEM ((2 * 128 * 68 + 64 * 68) * sizeof(float))

__global__ __launch_bounds__(256) void attn_kernel() {
    extern __shared__ float sm[];
    float* Qt = sm;                   // [128][68]
    float* Kt = sm + 128 * 68;        // [128][68] / as V: [64][128]
    float* Ps = sm + 2 * 128 * 68;    // [64][68]

    const int qt = blockIdx.x, h = blockIdx.y;
    const int tid = threadIdx.x, tx = tid & 15, ty = tid >> 4;
    const int q0 = qt * 64;
    const float scale = 0.088388347648318447f;

    const float* Qg = g_q + (size_t)q0 * DM + h * DH;
    for (int i = tid; i < 64 * 32; i += 256) {
        const int r = i & 63, c4 = i >> 6;
        float4 v = *(const float4*)(Qg + (size_t)r * DM + c4 * 4);
        const int d = c4 * 4;
        Qt[(d + 0) * 68 + r] = v.x; Qt[(d + 1) * 68 + r] = v.y;
        Qt[(d + 2) * 68 + r] = v.z; Qt[(d + 3) * 68 + r] = v.w;
    }

    float m_i[4], l_i[4], acc[4][8];
#pragma unroll
    for (int r = 0; r < 4; r++) {
        m_i[r] = -1e30f; l_i[r] = 0.f;
#pragma unroll
        for (int j = 0; j < 8; j++) acc[r][j] = 0.f;
    }

    for (int kt = 0; kt <= qt; kt++) {
        const int k0 = kt * 64;
        __syncthreads();
        const float* Kg = g_k + (size_t)k0 * DM + h * DH;
        for (int i = tid; i < 64 * 32; i += 256) {
            const int r = i & 63, c4 = i >> 6;
            float4 v = *(const float4*)(Kg + (size_t)r * DM + c4 * 4);
            const int d = c4 * 4;
            Kt[(d + 0) * 68 + r] = v.x; Kt[(d + 1) * 68 + r] = v.y;
            Kt[(d + 2) * 68 + r] = v.z; Kt[(d + 3) * 68 + r] = v.w;
        }
        __syncthreads();

        float s[4][4];
#pragma unroll
        for (int r = 0; r < 4; r++)
#pragma unroll
            for (int c = 0; c < 4; c++) s[r][c] = 0.f;

#pragma unroll 8
        for (int d = 0; d < DH; d++) {
            float qa[4], ka[4];
            *(float4*)qa = *(const float4*)&Qt[d * 68 + ty * 4];
            *(float4*)ka = *(const float4*)&Kt[d * 68 + tx * 4];
#pragma unroll
            for (int r = 0; r < 4; r++)
#pragma unroll
                for (int c = 0; c < 4; c++) s[r][c] += qa[r] * ka[c];
        }

#pragma unroll
        for (int r = 0; r < 4; r++) {
            const int qi = q0 + ty * 4 + r;
#pragma unroll
            for (int c = 0; c < 4; c++) {
                const int kj = k0 + tx * 4 + c;
                s[r][c] = (kj > qi) ? -1e30f : s[r][c] * scale;
            }
        }

#pragma unroll
        for (int r = 0; r < 4; r++) {
            float mx = fmaxf(fmaxf(s[r][0], s[r][1]), fmaxf(s[r][2], s[r][3]));
#pragma unroll
            for (int o = 8; o > 0; o >>= 1)
                mx = fmaxf(mx, __shfl_xor_sync(0xffffffffu, mx, o));
            const float mn = fmaxf(m_i[r], mx);
            const float alpha = __expf(m_i[r] - mn);
            m_i[r] = mn;
            float rs = 0.f;
#pragma unroll
            for (int c = 0; c < 4; c++) {
                const float p = __expf(s[r][c] - mn);
                Ps[(ty * 4 + r) * 68 + tx * 4 + c] = p;
                rs += p;
            }
#pragma unroll
            for (int o = 8; o > 0; o >>= 1)
                rs += __shfl_xor_sync(0xffffffffu, rs, o);
            l_i[r] = l_i[r] * alpha + rs;
#pragma unroll
            for (int j = 0; j < 8; j++) acc[r][j] *= alpha;
        }
        __syncthreads();

        const float* Vg = g_v + (size_t)k0 * DM + h * DH;
        for (int i = tid; i < 64 * 32; i += 256) {
            ((float4*)Kt)[i] = *(const float4*)(Vg + (size_t)(i >> 5) * DM + (i & 31) * 4);
        }
        __syncthreads();

#pragma unroll 4
        for (int c = 0; c < 64; c++) {
            float4 v0 = *(const float4*)&Kt[c * DH + tx * 8];
            float4 v1 = *(const float4*)&Kt[c * DH + tx * 8 + 4];
#pragma unroll
            for (int r = 0; r < 4; r++) {
                const float p = Ps[(ty * 4 + r) * 68 + c];
                acc[r][0] += p * v0.x; acc[r][1] += p * v0.y;
                acc[r][2] += p * v0.z; acc[r][3] += p * v0.w;
                acc[r][4] += p * v1.x; acc[r][5] += p * v1.y;
                acc[r][6] += p * v1.z; acc[r][7] += p * v1.w;
            }
        }
    }

    // epilogue: write attention output as bf16 hi/lo (feeds O-proj tensor GEMM)
#pragma unroll
    for (int r = 0; r < 4; r++) {
        const float invl = 1.f / l_i[r];
        const size_t base = (size_t)(q0 + ty * 4 + r) * DM + h * DH + tx * 8;
#pragma unroll
        for (int j = 0; j < 8; j++) {
            const float o = acc[r][j] * invl;
            __nv_bfloat16 hi = __float2bfloat16(o);
            g_ath[base + j] = hi;
            g_atl[base + j] = __float2bfloat16(o - __bfloat162float(hi));
        }
    }
}

// ===================== launcher ==============================================
extern "C" void kernel_launch(void* const* d_in, const int* in_sizes, int n_in,
                              void* d_out, int out_size) {
    const float* x    = (const float*)d_in[0];
    const float* w_ln = (const float*)d_in[1];
    const float* wq   = (const float*)d_in[2];
    const float* wk   = (const float*)d_in[3];
    const float* wv   = (const float*)d_in[4];
    const float* wo   = (const float*)d_in[5];
    const float* cosb = (const float*)d_in[6];
    const float* sinb = (const float*)d_in[7];
    float* out = (float*)d_out;

    (void)cudaFuncSetAttribute(attn_kernel,
                               cudaFuncAttributeMaxDynamicSharedMemorySize,
                               (int)ATTN_SMEM);

    float *p_q, *p_k, *p_v;
    __nv_bfloat16 *p_hh, *p_hl, *p_ath, *p_atl;
    __nv_bfloat16 *p_wqh, *p_wql, *p_wkh, *p_wkl, *p_wvh, *p_wvl, *p_woh, *p_wol;
    (void)cudaGetSymbolAddress((void**)&p_q, g_q);
    (void)cudaGetSymbolAddress((void**)&p_k, g_k);
    (void)cudaGetSymbolAddress((void**)&p_v, g_v);
    (void)cudaGetSymbolAddress((void**)&p_hh, g_hh);
    (void)cudaGetSymbolAddress((void**)&p_hl, g_hl);
    (void)cudaGetSymbolAddress((void**)&p_ath, g_ath);
    (void)cudaGetSymbolAddress((void**)&p_atl, g_atl);
    (void)cudaGetSymbolAddress((void**)&p_wqh, g_wqh);
    (void)cudaGetSymbolAddress((void**)&p_wql, g_wql);
    (void)cudaGetSymbolAddress((void**)&p_wkh, g_wkh);
    (void)cudaGetSymbolAddress((void**)&p_wkl, g_wkl);
    (void)cudaGetSymbolAddress((void**)&p_wvh, g_wvh);
    (void)cudaGetSymbolAddress((void**)&p_wvl, g_wvl);
    (void)cudaGetSymbolAddress((void**)&p_woh, g_woh);
    (void)cudaGetSymbolAddress((void**)&p_wol, g_wol);

    const int split_grid = (DM * DM / 4) / 256;  // 4096
    split_kernel<<<split_grid, 256>>>(wq, p_wqh, p_wql);
    split_kernel<<<split_grid, 256>>>(wk, p_wkh, p_wkl);
    split_kernel<<<split_grid, 256>>>(wv, p_wvh, p_wvl);
    split_kernel<<<split_grid, 256>>>(wo, p_woh, p_wol);

    rmsnorm_kernel<<<TT, 256>>>(x, w_ln);

    const dim3 gemm_grid(16, 16);
    gemm_mma_kernel<<<gemm_grid, 256>>>(p_hh, p_hl, p_wqh, p_wql, p_q, nullptr);
    gemm_mma_kernel<<<gemm_grid, 256>>>(p_hh, p_hl, p_wkh, p_wkl, p_k, nullptr);
    gemm_mma_kernel<<<gemm_grid, 256>>>(p_hh, p_hl, p_wvh, p_wvl, p_v, nullptr);

    rope_kernel<<<(TT * NH * 64) / 256, 256>>>(cosb, sinb);
    attn_kernel<<<dim3(TT / 64, NH), 256, ATTN_SMEM>>>();

    gemm_mma_kernel<<<gemm_grid, 256>>>(p_ath, p_atl, p_woh, p_wol, out, x);
}

// round 5
// speedup vs baseline: 2.7656x; 1.8276x over previous
#include <cuda_runtime.h>
#include <cuda_bf16.h>
#include <cstdint>
#include <math.h>

#define TT 2048
#define DM 2048
#define NH 16
#define DH 128

// ===================== PTX helpers ==========================================
__device__ __forceinline__ uint32_t smem_u32(const void* p) {
    uint32_t a;
    asm("{ .reg .u64 t; cvta.to.shared.u64 t, %1; cvt.u32.u64 %0, t; }"
        : "=r"(a) : "l"(p));
    return a;
}

#define CPASYNC16(dst, src) \
    asm volatile("cp.async.cg.shared.global [%0], [%1], 16;" :: "r"(dst), "l"(src))
#define CPASYNC8(dst, src) \
    asm volatile("cp.async.ca.shared.global [%0], [%1], 8;" :: "r"(dst), "l"(src))
#define CP_COMMIT() asm volatile("cp.async.commit_group;" ::: "memory")
#define CP_WAIT0() asm volatile("cp.async.wait_group 0;" ::: "memory")
#define CP_WAIT1() asm volatile("cp.async.wait_group 1;" ::: "memory")

#define LDMAT_X2_T(b0, b1, addr) \
    asm volatile("ldmatrix.sync.aligned.m8n8.x2.trans.shared.b16 {%0,%1}, [%2];" \
                 : "=r"(b0), "=r"(b1) : "r"(addr))

__device__ __forceinline__ void mma_bf16(float* c, uint32_t a0, uint32_t a1,
                                         uint32_t a2, uint32_t a3,
                                         uint32_t b0, uint32_t b1) {
    asm volatile(
        "mma.sync.aligned.m16n8k16.row.col.f32.bf16.bf16.f32 "
        "{%0,%1,%2,%3}, {%4,%5,%6,%7}, {%8,%9}, {%0,%1,%2,%3};"
        : "+f"(c[0]), "+f"(c[1]), "+f"(c[2]), "+f"(c[3])
        : "r"(a0), "r"(a1), "r"(a2), "r"(a3), "r"(b0), "r"(b1));
}

__device__ __forceinline__ uint32_t pack_bf16(float a, float b) {
    __nv_bfloat162 t = __floats2bfloat162_rn(a, b);
    return *(uint32_t*)&t;
}

#define LD32(p) (*(const uint32_t*)(p))

// ===================== scratch (static device globals) =======================
__device__ float g_q[(size_t)TT * DM];
__device__ float g_k[(size_t)TT * DM];
__device__ float g_v[(size_t)TT * DM];
__device__ __nv_bfloat16 g_hh[(size_t)TT * DM], g_hl[(size_t)TT * DM];
__device__ __nv_bfloat16 g_ath[(size_t)TT * DM], g_atl[(size_t)TT * DM];
__device__ __nv_bfloat16 g_qh[(size_t)TT * DM], g_ql[(size_t)TT * DM];
__device__ __nv_bfloat16 g_kh[(size_t)TT * DM], g_kl[(size_t)TT * DM];
__device__ __nv_bfloat16 g_vh[(size_t)TT * DM], g_vl[(size_t)TT * DM];
__device__ __nv_bfloat16 g_wqh[(size_t)DM * DM], g_wql[(size_t)DM * DM];
__device__ __nv_bfloat16 g_wkh[(size_t)DM * DM], g_wkl[(size_t)DM * DM];
__device__ __nv_bfloat16 g_wvh[(size_t)DM * DM], g_wvl[(size_t)DM * DM];
__device__ __nv_bfloat16 g_woh[(size_t)DM * DM], g_wol[(size_t)DM * DM];

// ===================== split fp32 -> bf16 hi/lo ==============================
__global__ __launch_bounds__(256) void split_kernel(const float* __restrict__ X,
                                                    __nv_bfloat16* __restrict__ Hi,
                                                    __nv_bfloat16* __restrict__ Lo) {
    const int i = (blockIdx.x * 256 + threadIdx.x) * 4;
    float4 v = *(const float4*)(X + i);
    float f[4] = {v.x, v.y, v.z, v.w};
    unsigned short hb[4], lb[4];
#pragma unroll
    for (int j = 0; j < 4; j++) {
        __nv_bfloat16 h = __float2bfloat16(f[j]);
        __nv_bfloat16 l = __float2bfloat16(f[j] - __bfloat162float(h));
        hb[j] = __bfloat16_as_ushort(h);
        lb[j] = __bfloat16_as_ushort(l);
    }
    uint2 hv, lv;
    hv.x = (uint32_t)hb[0] | ((uint32_t)hb[1] << 16);
    hv.y = (uint32_t)hb[2] | ((uint32_t)hb[3] << 16);
    lv.x = (uint32_t)lb[0] | ((uint32_t)lb[1] << 16);
    lv.y = (uint32_t)lb[2] | ((uint32_t)lb[3] << 16);
    *(uint2*)(Hi + i) = hv;
    *(uint2*)(Lo + i) = lv;
}

// ===================== RMSNorm (emits bf16 hi/lo) ============================
__global__ __launch_bounds__(256) void rmsnorm_kernel(const float* __restrict__ x,
                                                      const float* __restrict__ w) {
    __shared__ float red[256];
    const int row = blockIdx.x;
    const int tid = threadIdx.x;
    const float* xr = x + (size_t)row * DM;
    float s = 0.f;
    for (int i = tid; i < DM; i += 256) { float v = xr[i]; s += v * v; }
    red[tid] = s;
    __syncthreads();
    for (int o = 128; o > 0; o >>= 1) {
        if (tid < o) red[tid] += red[tid + o];
        __syncthreads();
    }
    const float inv = rsqrtf(red[0] / (float)DM + 1e-5f);
    __nv_bfloat16* hh = g_hh + (size_t)row * DM;
    __nv_bfloat16* hl = g_hl + (size_t)row * DM;
    for (int i = tid; i < DM; i += 256) {
        float y = w[i] * xr[i] * inv;
        __nv_bfloat16 h = __float2bfloat16(y);
        hh[i] = h;
        hl[i] = __float2bfloat16(y - __bfloat162float(h));
    }
}

// ===================== split-bf16 tensor GEMM (cp.async pipelined) ===========
// C[M,N] = (Ah+Al)(Bh+Bl)^T dropping AlBl. CTA 128x128, BK=32, 8 warps (2x4).
#define SPAD 40
#define GTILE (128 * SPAD)   // 5120 elems
#define GSTG (4 * GTILE)     // 20480 elems per stage
#define GEMM_SMEM (2 * GSTG * 2)  // bytes = 81920

__device__ __forceinline__ void gemm_load_stage(
    uint32_t sbase, int st,
    const __nv_bfloat16* Ah, const __nv_bfloat16* Al,
    const __nv_bfloat16* Bh, const __nv_bfloat16* Bl,
    int m0, int n0, int k0, int tid) {
    const __nv_bfloat16* gp[4] = {
        Ah + (size_t)m0 * DM + k0, Al + (size_t)m0 * DM + k0,
        Bh + (size_t)n0 * DM + k0, Bl + (size_t)n0 * DM + k0};
#pragma unroll
    for (int t4 = 0; t4 < 4; t4++) {
#pragma unroll
        for (int i = 0; i < 4; i++) {
            const int idx = i * 256 + tid;          // 0..1023
            const int r = idx >> 3, c = idx & 7;    // 128 rows x 8 chunks(4 bf16)
            const uint32_t dst = sbase + (uint32_t)((st * 4 + t4) * GTILE + r * SPAD + c * 4) * 2;
            const void* src = gp[t4] + (size_t)r * DM + c * 4;
            CPASYNC8(dst, src);
        }
    }
}

__global__ __launch_bounds__(256) void gemm_mma_kernel(
    const __nv_bfloat16* __restrict__ Ah, const __nv_bfloat16* __restrict__ Al,
    const __nv_bfloat16* __restrict__ Bh, const __nv_bfloat16* __restrict__ Bl,
    float* __restrict__ C, const float* __restrict__ R) {
    extern __shared__ __nv_bfloat16 dynsm[];
    const uint32_t sbase = smem_u32(dynsm);
    const int tid = threadIdx.x;
    const int wid = tid >> 5, lane = tid & 31;
    const int gg = lane >> 2, tg = lane & 3;
    const int wm = (wid >> 2) * 64, wn = (wid & 3) * 32;
    const int m0 = blockIdx.y * 128, n0 = blockIdx.x * 128;

    float acc[4][4][4];
#pragma unroll
    for (int mt = 0; mt < 4; mt++)
#pragma unroll
        for (int nt = 0; nt < 4; nt++)
#pragma unroll
            for (int j = 0; j < 4; j++) acc[mt][nt][j] = 0.f;

    gemm_load_stage(sbase, 0, Ah, Al, Bh, Bl, m0, n0, 0, tid);
    CP_COMMIT();

    for (int c = 0; c < DM / 32; c++) {
        if (c + 1 < DM / 32) {
            gemm_load_stage(sbase, (c + 1) & 1, Ah, Al, Bh, Bl, m0, n0, (c + 1) * 32, tid);
            CP_COMMIT();
            CP_WAIT1();
        } else {
            CP_WAIT0();
        }
        __syncthreads();

        const __nv_bfloat16* pAh = dynsm + (c & 1) * GSTG;
        const __nv_bfloat16* pAl = pAh + GTILE;
        const __nv_bfloat16* pBh = pAh + 2 * GTILE;
        const __nv_bfloat16* pBl = pAh + 3 * GTILE;

#pragma unroll
        for (int ks = 0; ks < 32; ks += 16) {
            uint32_t ah[4][4], al[4][4], bh[4][2], bl[4][2];
#pragma unroll
            for (int mt = 0; mt < 4; mt++) {
                const int row = wm + mt * 16;
                ah[mt][0] = LD32(pAh + (row + gg) * SPAD + ks + tg * 2);
                ah[mt][1] = LD32(pAh + (row + gg + 8) * SPAD + ks + tg * 2);
                ah[mt][2] = LD32(pAh + (row + gg) * SPAD + ks + tg * 2 + 8);
                ah[mt][3] = LD32(pAh + (row + gg + 8) * SPAD + ks + tg * 2 + 8);
                al[mt][0] = LD32(pAl + (row + gg) * SPAD + ks + tg * 2);
                al[mt][1] = LD32(pAl + (row + gg + 8) * SPAD + ks + tg * 2);
                al[mt][2] = LD32(pAl + (row + gg) * SPAD + ks + tg * 2 + 8);
                al[mt][3] = LD32(pAl + (row + gg + 8) * SPAD + ks + tg * 2 + 8);
            }
#pragma unroll
            for (int nt = 0; nt < 4; nt++) {
                const int col = wn + nt * 8;
                bh[nt][0] = LD32(pBh + (col + gg) * SPAD + ks + tg * 2);
                bh[nt][1] = LD32(pBh + (col + gg) * SPAD + ks + tg * 2 + 8);
                bl[nt][0] = LD32(pBl + (col + gg) * SPAD + ks + tg * 2);
                bl[nt][1] = LD32(pBl + (col + gg) * SPAD + ks + tg * 2 + 8);
            }
#pragma unroll
            for (int mt = 0; mt < 4; mt++)
#pragma unroll
                for (int nt = 0; nt < 4; nt++) {
                    mma_bf16(acc[mt][nt], ah[mt][0], ah[mt][1], ah[mt][2], ah[mt][3],
                             bh[nt][0], bh[nt][1]);
                    mma_bf16(acc[mt][nt], ah[mt][0], ah[mt][1], ah[mt][2], ah[mt][3],
                             bl[nt][0], bl[nt][1]);
                    mma_bf16(acc[mt][nt], al[mt][0], al[mt][1], al[mt][2], al[mt][3],
                             bh[nt][0], bh[nt][1]);
                }
        }
        __syncthreads();
    }

#pragma unroll
    for (int mt = 0; mt < 4; mt++) {
        const int mA = m0 + wm + mt * 16 + gg;
        const int mB = mA + 8;
#pragma unroll
        for (int nt = 0; nt < 4; nt++) {
            const int n = n0 + wn + nt * 8 + tg * 2;
            float2 v0 = make_float2(acc[mt][nt][0], acc[mt][nt][1]);
            float2 v1 = make_float2(acc[mt][nt][2], acc[mt][nt][3]);
            if (R) {
                float2 r0 = *(const float2*)(R + (size_t)mA * DM + n);
                float2 r1 = *(const float2*)(R + (size_t)mB * DM + n);
                v0.x += r0.x; v0.y += r0.y;
                v1.x += r1.x; v1.y += r1.y;
            }
            *(float2*)(C + (size_t)mA * DM + n) = v0;
            *(float2*)(C + (size_t)mB * DM + n) = v1;
        }
    }
}

// ===================== RoPE -> bf16 hi/lo q,k ================================
__global__ __launch_bounds__(256) void rope_split_kernel(const float* __restrict__ cosb,
                                                         const float* __restrict__ sinb) {
    const int idx = blockIdx.x * 256 + threadIdx.x;
    const int t = idx >> 10;
    const int rem = idx & 1023;
    const int h = rem >> 6;
    const int j = rem & 63;
    const size_t base = (size_t)t * DM + h * DH;
    const float c0 = cosb[t * DH + j],      s0 = sinb[t * DH + j];
    const float c1 = cosb[t * DH + 64 + j], s1 = sinb[t * DH + 64 + j];

    float q0 = g_q[base + j], q1 = g_q[base + 64 + j];
    float k0 = g_k[base + j], k1 = g_k[base + 64 + j];
    float qa = q0 * c0 - q1 * s0, qb = q1 * c1 + q0 * s1;
    float ka = k0 * c0 - k1 * s0, kb = k1 * c1 + k0 * s1;

    __nv_bfloat16 hqa = __float2bfloat16(qa), hqb = __float2bfloat16(qb);
    __nv_bfloat16 hka = __float2bfloat16(ka), hkb = __float2bfloat16(kb);
    g_qh[base + j] = hqa;      g_ql[base + j] = __float2bfloat16(qa - __bfloat162float(hqa));
    g_qh[base + 64 + j] = hqb; g_ql[base + 64 + j] = __float2bfloat16(qb - __bfloat162float(hqb));
    g_kh[base + j] = hka;      g_kl[base + j] = __float2bfloat16(ka - __bfloat162float(hka));
    g_kh[base + 64 + j] = hkb; g_kl[base + 64 + j] = __float2bfloat16(kb - __bfloat162float(hkb));
}

// ===================== flash attention via mma.sync ==========================
// 64-query tile, 4 warps (16 rows each). K/V tiles of 64 via cp.async.
// smem (bf16 elems): Qh Ql Kh Kl Vh Vl, each [64][136].
#define AROW 136
#define ATILE (64 * AROW)      // 8704 elems
#define ATTN_SMEM (6 * ATILE * 2)  // 104448 bytes

__device__ __forceinline__ void attn_load64(uint32_t sbase, int elem_off,
                                            const __nv_bfloat16* g, int tid) {
#pragma unroll
    for (int t = 0; t < 8; t++) {
        const int idx = t * 128 + tid;          // 0..1023
        const int r = idx >> 4, c = idx & 15;   // 64 rows x 16 chunks(8 bf16)
        const uint32_t dst = sbase + (uint32_t)(elem_off + r * AROW + c * 8) * 2;
        const void* src = g + (size_t)r * DM + c * 8;
        CPASYNC16(dst, src);
    }
}

__global__ __launch_bounds__(128) void attn_mma_kernel() {
    extern __shared__ __nv_bfloat16 dynsm[];
    const uint32_t sbase = smem_u32(dynsm);
    const int QH = 0, QL = ATILE, KH = 2 * ATILE, KL = 3 * ATILE,
              VH = 4 * ATILE, VL = 5 * ATILE;
    const int qt = blockIdx.x, h = blockIdx.y;
    const int tid = threadIdx.x, wid = tid >> 5, lane = tid & 31;
    const int gg = lane >> 2, tg = lane & 3;
    const int q0 = qt * 64, wr = wid * 16;
    const float scale = 0.08838834764831845f;  // 1/sqrt(128)

    attn_load64(sbase, QH, g_qh + (size_t)q0 * DM + h * DH, tid);
    attn_load64(sbase, QL, g_ql + (size_t)q0 * DM + h * DH, tid);
    CP_COMMIT();
    CP_WAIT0();
    __syncthreads();

    float m0 = -1e30f, m1 = -1e30f, l0 = 0.f, l1 = 0.f;
    float o[16][4];
#pragma unroll
    for (int nt = 0; nt < 16; nt++)
#pragma unroll
        for (int j = 0; j < 4; j++) o[nt][j] = 0.f;

    for (int kt = 0; kt <= qt; kt++) {
        const int k0 = kt * 64;
        attn_load64(sbase, KH, g_kh + (size_t)k0 * DM + h * DH, tid);
        attn_load64(sbase, KL, g_kl + (size_t)k0 * DM + h * DH, tid);
        CP_COMMIT();
        attn_load64(sbase, VH, g_vh + (size_t)k0 * DM + h * DH, tid);
        attn_load64(sbase, VL, g_vl + (size_t)k0 * DM + h * DH, tid);
        CP_COMMIT();
        CP_WAIT1();           // K ready (V may still be in flight)
        __syncthreads();

        // ---- S = Q K^T (split 3-product) ----
        float s[8][4];
#pragma unroll
        for (int nt = 0; nt < 8; nt++)
#pragma unroll
            for (int j = 0; j < 4; j++) s[nt][j] = 0.f;

#pragma unroll
        for (int ks = 0; ks < 8; ks++) {
            const int kk = ks * 16;
            const __nv_bfloat16* qh = dynsm + QH;
            const __nv_bfloat16* ql = dynsm + QL;
            const __nv_bfloat16* kh = dynsm + KH;
            const __nv_bfloat16* kl = dynsm + KL;
            uint32_t ah0 = LD32(qh + (wr + gg) * AROW + kk + tg * 2);
            uint32_t ah1 = LD32(qh + (wr + gg + 8) * AROW + kk + tg * 2);
            uint32_t ah2 = LD32(qh + (wr + gg) * AROW + kk + tg * 2 + 8);
            uint32_t ah3 = LD32(qh + (wr + gg + 8) * AROW + kk + tg * 2 + 8);
            uint32_t al0 = LD32(ql + (wr + gg) * AROW + kk + tg * 2);
            uint32_t al1 = LD32(ql + (wr + gg + 8) * AROW + kk + tg * 2);
            uint32_t al2 = LD32(ql + (wr + gg) * AROW + kk + tg * 2 + 8);
            uint32_t al3 = LD32(ql + (wr + gg + 8) * AROW + kk + tg * 2 + 8);
#pragma unroll
            for (int nt = 0; nt < 8; nt++) {
                uint32_t bh0 = LD32(kh + (nt * 8 + gg) * AROW + kk + tg * 2);
                uint32_t bh1 = LD32(kh + (nt * 8 + gg) * AROW + kk + tg * 2 + 8);
                uint32_t bl0 = LD32(kl + (nt * 8 + gg) * AROW + kk + tg * 2);
                uint32_t bl1 = LD32(kl + (nt * 8 + gg) * AROW + kk + tg * 2 + 8);
                mma_bf16(s[nt], ah0, ah1, ah2, ah3, bh0, bh1);
                mma_bf16(s[nt], ah0, ah1, ah2, ah3, bl0, bl1);
                mma_bf16(s[nt], al0, al1, al2, al3, bh0, bh1);
            }
        }

        // ---- scale + causal mask ----
        if (kt == qt) {
            const int r0i = wr + gg, r1i = r0i + 8;
#pragma unroll
            for (int nt = 0; nt < 8; nt++) {
                const int c0 = nt * 8 + tg * 2, c1 = c0 + 1;
                s[nt][0] = (c0 > r0i) ? -1e30f : s[nt][0] * scale;
                s[nt][1] = (c1 > r0i) ? -1e30f : s[nt][1] * scale;
                s[nt][2] = (c0 > r1i) ? -1e30f : s[nt][2] * scale;
                s[nt][3] = (c1 > r1i) ? -1e30f : s[nt][3] * scale;
            }
        } else {
#pragma unroll
            for (int nt = 0; nt < 8; nt++)
#pragma unroll
                for (int j = 0; j < 4; j++) s[nt][j] *= scale;
        }

        // ---- online softmax (rows gg and gg+8; quad = lanes sharing gg) ----
        float mx0 = -1e30f, mx1 = -1e30f;
#pragma unroll
        for (int nt = 0; nt < 8; nt++) {
            mx0 = fmaxf(mx0, fmaxf(s[nt][0], s[nt][1]));
            mx1 = fmaxf(mx1, fmaxf(s[nt][2], s[nt][3]));
        }
        mx0 = fmaxf(mx0, __shfl_xor_sync(0xffffffffu, mx0, 1));
        mx0 = fmaxf(mx0, __shfl_xor_sync(0xffffffffu, mx0, 2));
        mx1 = fmaxf(mx1, __shfl_xor_sync(0xffffffffu, mx1, 1));
        mx1 = fmaxf(mx1, __shfl_xor_sync(0xffffffffu, mx1, 2));
        const float mn0 = fmaxf(m0, mx0), mn1 = fmaxf(m1, mx1);
        const float a0 = __expf(m0 - mn0), a1 = __expf(m1 - mn1);
        m0 = mn0; m1 = mn1;
        float rs0 = 0.f, rs1 = 0.f;
#pragma unroll
        for (int nt = 0; nt < 8; nt++) {
            s[nt][0] = __expf(s[nt][0] - mn0); rs0 += s[nt][0];
            s[nt][1] = __expf(s[nt][1] - mn0); rs0 += s[nt][1];
            s[nt][2] = __expf(s[nt][2] - mn1); rs1 += s[nt][2];
            s[nt][3] = __expf(s[nt][3] - mn1); rs1 += s[nt][3];
        }
        rs0 += __shfl_xor_sync(0xffffffffu, rs0, 1);
        rs0 += __shfl_xor_sync(0xffffffffu, rs0, 2);
        rs1 += __shfl_xor_sync(0xffffffffu, rs1, 1);
        rs1 += __shfl_xor_sync(0xffffffffu, rs1, 2);
        l0 = l0 * a0 + rs0;
        l1 = l1 * a1 + rs1;
#pragma unroll
        for (int nt = 0; nt < 16; nt++) {
            o[nt][0] *= a0; o[nt][1] *= a0;
            o[nt][2] *= a1; o[nt][3] *= a1;
        }

        CP_WAIT0();           // V ready
        __syncthreads();

        // ---- O += P V (P split hi/lo, V split hi/lo; 3 products) ----
#pragma unroll
        for (int kp = 0; kp < 4; kp++) {
            const int j0 = kp * 2, j1 = j0 + 1;
            const float v00 = s[j0][0], v01 = s[j0][1], v02 = s[j0][2], v03 = s[j0][3];
            const float v10 = s[j1][0], v11 = s[j1][1], v12 = s[j1][2], v13 = s[j1][3];
            const float h00 = __bfloat162float(__float2bfloat16(v00));
            const float h01 = __bfloat162float(__float2bfloat16(v01));
            const float h02 = __bfloat162float(__float2bfloat16(v02));
            const float h03 = __bfloat162float(__float2bfloat16(v03));
            const float h10 = __bfloat162float(__float2bfloat16(v10));
            const float h11 = __bfloat162float(__float2bfloat16(v11));
            const float h12 = __bfloat162float(__float2bfloat16(v12));
            const float h13 = __bfloat162float(__float2bfloat16(v13));
            const uint32_t ph0 = pack_bf16(v00, v01), ph1 = pack_bf16(v02, v03);
            const uint32_t ph2 = pack_bf16(v10, v11), ph3 = pack_bf16(v12, v13);
            const uint32_t pl0 = pack_bf16(v00 - h00, v01 - h01);
            const uint32_t pl1 = pack_bf16(v02 - h02, v03 - h03);
            const uint32_t pl2 = pack_bf16(v10 - h10, v11 - h11);
            const uint32_t pl3 = pack_bf16(v12 - h12, v13 - h13);

            const uint32_t vrow_h =
                sbase + (uint32_t)(VH + (kp * 16 + (lane & 15)) * AROW) * 2;
            const uint32_t vrow_l =
                sbase + (uint32_t)(VL + (kp * 16 + (lane & 15)) * AROW) * 2;
#pragma unroll
            for (int nt = 0; nt < 16; nt++) {
                uint32_t bh0, bh1, bl0, bl1;
                LDMAT_X2_T(bh0, bh1, vrow_h + nt * 16);
                LDMAT_X2_T(bl0, bl1, vrow_l + nt * 16);
                mma_bf16(o[nt], ph0, ph1, ph2, ph3, bh0, bh1);
                mma_bf16(o[nt], ph0, ph1, ph2, ph3, bl0, bl1);
                mma_bf16(o[nt], pl0, pl1, pl2, pl3, bh0, bh1);
            }
        }
        __syncthreads();      // before next iteration overwrites K/V smem
    }

    // ---- epilogue: normalize, write bf16 hi/lo ----
    const float inv0 = 1.f / l0, inv1 = 1.f / l1;
    const int r0 = q0 + wr + gg, r1 = r0 + 8;
    const int colb = h * DH + tg * 2;
#pragma unroll
    for (int nt = 0; nt < 16; nt++) {
        const int col = colb + nt * 8;
        const float f0 = o[nt][0] * inv0, f1 = o[nt][1] * inv0;
        const float f2 = o[nt][2] * inv1, f3 = o[nt][3] * inv1;
        const float h0 = __bfloat162float(__float2bfloat16(f0));
        const float h1 = __bfloat162float(__float2bfloat16(f1));
        const float h2 = __bfloat162float(__float2bfloat16(f2));
        const float h3 = __bfloat162float(__float2bfloat16(f3));
        *(uint32_t*)&g_ath[(size_t)r0 * DM + col] = pack_bf16(f0, f1);
        *(uint32_t*)&g_atl[(size_t)r0 * DM + col] = pack_bf16(f0 - h0, f1 - h1);
        *(uint32_t*)&g_ath[(size_t)r1 * DM + col] = pack_bf16(f2, f3);
        *(uint32_t*)&g_atl[(size_t)r1 * DM + col] = pack_bf16(f2 - h2, f3 - h3);
    }
}

// ===================== launcher ==============================================
extern "C" void kernel_launch(void* const* d_in, const int* in_sizes, int n_in,
                              void* d_out, int out_size) {
    const float* x    = (const float*)d_in[0];
    const float* w_ln = (const float*)d_in[1];
    const float* wq   = (const float*)d_in[2];
    const float* wk   = (const float*)d_in[3];
    const float* wv   = (const float*)d_in[4];
    const float* wo   = (const float*)d_in[5];
    const float* cosb = (const float*)d_in[6];
    const float* sinb = (const float*)d_in[7];
    float* out = (float*)d_out;

    (void)cudaFuncSetAttribute(gemm_mma_kernel,
                               cudaFuncAttributeMaxDynamicSharedMemorySize, GEMM_SMEM);
    (void)cudaFuncSetAttribute(attn_mma_kernel,
                               cudaFuncAttributeMaxDynamicSharedMemorySize, ATTN_SMEM);

    float *p_q, *p_k, *p_v;
    __nv_bfloat16 *p_hh, *p_hl, *p_ath, *p_atl, *p_vh, *p_vl;
    __nv_bfloat16 *p_wqh, *p_wql, *p_wkh, *p_wkl, *p_wvh, *p_wvl, *p_woh, *p_wol;
    (void)cudaGetSymbolAddress((void**)&p_q, g_q);
    (void)cudaGetSymbolAddress((void**)&p_k, g_k);
    (void)cudaGetSymbolAddress((void**)&p_v, g_v);
    (void)cudaGetSymbolAddress((void**)&p_hh, g_hh);
    (void)cudaGetSymbolAddress((void**)&p_hl, g_hl);
    (void)cudaGetSymbolAddress((void**)&p_ath, g_ath);
    (void)cudaGetSymbolAddress((void**)&p_atl, g_atl);
    (void)cudaGetSymbolAddress((void**)&p_vh, g_vh);
    (void)cudaGetSymbolAddress((void**)&p_vl, g_vl);
    (void)cudaGetSymbolAddress((void**)&p_wqh, g_wqh);
    (void)cudaGetSymbolAddress((void**)&p_wql, g_wql);
    (void)cudaGetSymbolAddress((void**)&p_wkh, g_wkh);
    (void)cudaGetSymbolAddress((void**)&p_wkl, g_wkl);
    (void)cudaGetSymbolAddress((void**)&p_wvh, g_wvh);
    (void)cudaGetSymbolAddress((void**)&p_wvl, g_wvl);
    (void)cudaGetSymbolAddress((void**)&p_woh, g_woh);
    (void)cudaGetSymbolAddress((void**)&p_wol, g_wol);

    const int split_grid = (DM * DM / 4) / 256;  // 4096
    split_kernel<<<split_grid, 256>>>(wq, p_wqh, p_wql);
    split_kernel<<<split_grid, 256>>>(wk, p_wkh, p_wkl);
    split_kernel<<<split_grid, 256>>>(wv, p_wvh, p_wvl);
    split_kernel<<<split_grid, 256>>>(wo, p_woh, p_wol);

    rmsnorm_kernel<<<TT, 256>>>(x, w_ln);

    const dim3 gemm_grid(16, 16);
    gemm_mma_kernel<<<gemm_grid, 256, GEMM_SMEM>>>(p_hh, p_hl, p_wqh, p_wql, p_q, nullptr);
    gemm_mma_kernel<<<gemm_grid, 256, GEMM_SMEM>>>(p_hh, p_hl, p_wkh, p_wkl, p_k, nullptr);
    gemm_mma_kernel<<<gemm_grid, 256, GEMM_SMEM>>>(p_hh, p_hl, p_wvh, p_wvl, p_v, nullptr);

    split_kernel<<<split_grid, 256>>>(p_v, p_vh, p_vl);
    rope_split_kernel<<<(TT * NH * 64) / 256, 256>>>(cosb, sinb);

    attn_mma_kernel<<<dim3(TT / 64, NH), 128, ATTN_SMEM>>>();

    gemm_mma_kernel<<<gemm_grid, 256, GEMM_SMEM>>>(p_ath, p_atl, p_woh, p_wol, out, x);
}